// round 6
// baseline (speedup 1.0000x reference)
#include <cuda_runtime.h>
#include <cuda_fp16.h>
#include <math.h>

#define NMAX 100000
#define C    64
#define HID  16
#define KNN  16
#define FULL 0xFFFFFFFFu

// Scratch (device globals)
__device__ float g_outse[(size_t)NMAX * C];
__device__ float g_rowstat[(size_t)NMAX * 2];
__device__ float g_z[(size_t)NMAX * 2];
__device__ float g_gate[(size_t)NMAX];
__device__ __align__(16) __half2 g_xh2[(size_t)NMAX * C / 2]; // fp16 mirror of x_F
__device__ __align__(4)  __half2 g_yh2[(size_t)NMAX * HID / 2]; // y = x@W1, fp16

// ---------------------------------------------------------------------------
// Kernel 0: per point, QUARTER-WARP: (a) fp16 mirror of x row (128B line),
//           (b) y = x @ W1 (16 fp16) for the linear mean path.
//   q = lane>>3, ql = lane&7, point n = 4*warp + q, lane owns ch 8ql..8ql+7.
// ---------------------------------------------------------------------------
__global__ __launch_bounds__(256) void k0_prep(
    const float* __restrict__ xF,
    const float* __restrict__ W1,   // (C, HID)
    int N)
{
    __shared__ float4 sW1a[HID * 8], sW1b[HID * 8];
    const int tid = threadIdx.x;
    for (int i = tid; i < HID * 8; i += blockDim.x) {
        int j = i >> 3, h = i & 7;
        sW1a[i] = make_float4(W1[(8*h+0)*HID + j], W1[(8*h+1)*HID + j],
                              W1[(8*h+2)*HID + j], W1[(8*h+3)*HID + j]);
        sW1b[i] = make_float4(W1[(8*h+4)*HID + j], W1[(8*h+5)*HID + j],
                              W1[(8*h+6)*HID + j], W1[(8*h+7)*HID + j]);
    }
    __syncthreads();

    const int lane = tid & 31;
    const int q    = lane >> 3;
    const int ql   = lane & 7;
    const int warp = blockIdx.x * (blockDim.x >> 5) + (tid >> 5);
    if (4 * warp >= N) return;
    int n = 4 * warp + q;
    if (n >= N) n = N - 1;

    // load fp32 row segment (8 channels)
    float4 xv0 = __ldg((const float4*)(xF + (size_t)n * C) + 2 * ql);
    float4 xv1 = __ldg((const float4*)(xF + (size_t)n * C) + 2 * ql + 1);

    // (a) fp16 mirror
    __half2 h0 = __floats2half2_rn(xv0.x, xv0.y);
    __half2 h1 = __floats2half2_rn(xv0.z, xv0.w);
    __half2 h2 = __floats2half2_rn(xv1.x, xv1.y);
    __half2 h3 = __floats2half2_rn(xv1.z, xv1.w);
    ((uint4*)(g_xh2 + (size_t)n * (C/2)))[ql] =
        make_uint4(*(unsigned*)&h0, *(unsigned*)&h1, *(unsigned*)&h2, *(unsigned*)&h3);

    // (b) y partials over this lane's 8 channels, then 8-lane butterfly
    float p[HID];
    #pragma unroll
    for (int j = 0; j < HID; j++) {
        float4 wa = sW1a[j * 8 + ql], wb = sW1b[j * 8 + ql];
        p[j] = xv0.x*wa.x + xv0.y*wa.y + xv0.z*wa.z + xv0.w*wa.w
             + xv1.x*wb.x + xv1.y*wb.y + xv1.z*wb.z + xv1.w*wb.w;
    }
    #pragma unroll
    for (int step = 0; step < 3; step++) {
        const int  off = 4 >> step;   // 4,2,1 (within quarter)
        const int  nv  = 8 >> step;   // 8,4,2
        const bool up  = (ql & off) != 0;
        #pragma unroll
        for (int i = 0; i < nv; i++) {
            float send = up ? p[i] : p[i + nv];
            float recv = __shfl_xor_sync(FULL, send, off);
            float keep = up ? p[i + nv] : p[i];
            p[i] = keep + recv;
        }
    }
    // lane ql holds y elements (2ql, 2ql+1)  [same mapping as k1's butterfly]
    g_yh2[(size_t)n * (HID/2) + ql] = __floats2half2_rn(p[0], p[1]);
}

// ---------------------------------------------------------------------------
// Kernel 1: channel attention, QUARTER-WARP per point.
//   Gather loop per k: 1 LDG.128 (fp16 x row, max path, HMAX2-pooled exactly)
//                    + 1 LDG.64 (fp16 y, mean path, HADD2-accumulated).
//   Max path layer-1 in fp32 after a single post-loop conversion.
// ---------------------------------------------------------------------------
__global__ __launch_bounds__(256) void k1_gate(
    const float* __restrict__ xF,
    const float* __restrict__ W1,   // (C, HID)
    const float* __restrict__ b1,   // (HID,)
    const float* __restrict__ W2,   // (HID, C)
    const float* __restrict__ b2,   // (C,)
    const int*   __restrict__ idx,  // (N, KNN)
    int N)
{
    __shared__ float4 sW1a[HID * 8], sW1b[HID * 8];
    __shared__ float4 sW2a[HID * 8], sW2b[HID * 8];

    const int tid = threadIdx.x;
    for (int i = tid; i < HID * 8; i += blockDim.x) {
        int j = i >> 3, h = i & 7;
        sW1a[i] = make_float4(W1[(8*h+0)*HID + j], W1[(8*h+1)*HID + j],
                              W1[(8*h+2)*HID + j], W1[(8*h+3)*HID + j]);
        sW1b[i] = make_float4(W1[(8*h+4)*HID + j], W1[(8*h+5)*HID + j],
                              W1[(8*h+6)*HID + j], W1[(8*h+7)*HID + j]);
        sW2a[i] = __ldg((const float4*)W2 + j * 16 + 2 * h);
        sW2b[i] = __ldg((const float4*)W2 + j * 16 + 2 * h + 1);
    }
    __syncthreads();

    const int lane  = tid & 31;
    const int q     = lane >> 3;
    const int ql    = lane & 7;
    const int qbase = lane & 24;
    const int warp  = blockIdx.x * (blockDim.x >> 5) + (tid >> 5);
    if (4 * warp >= N) return;
    int n = 4 * warp + q;
    if (n >= N) n = N - 1;

    const float2 b1v = __ldg((const float2*)b1 + ql);
    const float4 b2a = __ldg((const float4*)b2 + 2 * ql);
    const float4 b2b = __ldg((const float4*)b2 + 2 * ql + 1);

    // ---- neighbor indices ----
    const int4* ib = (const int4*)(idx + (size_t)n * KNN);
    int4 i0 = __ldg(ib + 0), i1 = __ldg(ib + 1),
         i2 = __ldg(ib + 2), i3 = __ldg(ib + 3);
    const int nb[KNN] = { i0.x, i0.y, i0.z, i0.w,  i1.x, i1.y, i1.z, i1.w,
                          i2.x, i2.y, i2.z, i2.w,  i3.x, i3.y, i3.z, i3.w };

    // ---- gather loop: half2 max pooling (exact) + half2 y-sum (mean path) ----
    const __half NEGINF = __ushort_as_half((unsigned short)0xFC00);
    __half2 mh0 = __half2half2(NEGINF), mh1 = __half2half2(NEGINF);
    __half2 mh2 = __half2half2(NEGINF), mh3 = __half2half2(NEGINF);
    __half2 ys  = __float2half2_rn(0.f);
    #pragma unroll
    for (int k = 0; k < KNN; k++) {
        uint4 raw = __ldg((const uint4*)(g_xh2 + (size_t)nb[k] * (C/2)) + ql);
        mh0 = __hmax2(mh0, *(__half2*)&raw.x);
        mh1 = __hmax2(mh1, *(__half2*)&raw.y);
        mh2 = __hmax2(mh2, *(__half2*)&raw.z);
        mh3 = __hmax2(mh3, *(__half2*)&raw.w);
        ys  = __hadd2(ys, __ldg(g_yh2 + (size_t)nb[k] * (HID/2) + ql));
    }

    // ---- max path: convert once, layer-1 FFMA + 8-lane butterfly ----
    float2 f0 = __half22float2(mh0), f1 = __half22float2(mh1);
    float2 f2 = __half22float2(mh2), f3 = __half22float2(mh3);
    float px[HID];
    #pragma unroll
    for (int j = 0; j < HID; j++) {
        float4 wa = sW1a[j * 8 + ql], wb = sW1b[j * 8 + ql];
        px[j] = f0.x*wa.x + f0.y*wa.y + f1.x*wa.z + f1.y*wa.w
              + f2.x*wb.x + f2.y*wb.y + f3.x*wb.z + f3.y*wb.w;
    }
    #pragma unroll
    for (int step = 0; step < 3; step++) {
        const int  off = 4 >> step;
        const int  nv  = 8 >> step;
        const bool up  = (ql & off) != 0;
        #pragma unroll
        for (int i = 0; i < nv; i++) {
            float send = up ? px[i] : px[i + nv];
            float recv = __shfl_xor_sync(FULL, send, off);
            float keep = up ? px[i + nv] : px[i];
            px[i] = keep + recv;
        }
    }
    // lane ql: px[0], px[1] = max-path pre-act for hidden 2ql, 2ql+1

    // ---- mean path: already in-lane via y-sum ----
    float2 ym = __half22float2(ys);
    const float invK = 1.f / KNN;
    float hs0 = fmaxf(ym.x * invK + b1v.x, 0.f) + fmaxf(px[0] + b1v.x, 0.f);
    float hs1 = fmaxf(ym.y * invK + b1v.y, 0.f) + fmaxf(px[1] + b1v.y, 0.f);

    // ---- layer 2 ----
    float4 a0 = make_float4(2.f*b2a.x, 2.f*b2a.y, 2.f*b2a.z, 2.f*b2a.w);
    float4 a1 = make_float4(2.f*b2b.x, 2.f*b2b.y, 2.f*b2b.z, 2.f*b2b.w);
    #pragma unroll
    for (int jj = 0; jj < 8; jj++) {
        float h0 = __shfl_sync(FULL, hs0, qbase | jj);   // hidden 2jj
        float h1 = __shfl_sync(FULL, hs1, qbase | jj);   // hidden 2jj+1
        float4 wa = sW2a[(2*jj) * 8 + ql],   wb = sW2b[(2*jj) * 8 + ql];
        a0.x += h0*wa.x; a0.y += h0*wa.y; a0.z += h0*wa.z; a0.w += h0*wa.w;
        a1.x += h0*wb.x; a1.y += h0*wb.y; a1.z += h0*wb.z; a1.w += h0*wb.w;
        float4 wc = sW2a[(2*jj+1) * 8 + ql], wd = sW2b[(2*jj+1) * 8 + ql];
        a0.x += h1*wc.x; a0.y += h1*wc.y; a0.z += h1*wc.z; a0.w += h1*wc.w;
        a1.x += h1*wd.x; a1.y += h1*wd.y; a1.z += h1*wd.z; a1.w += h1*wd.w;
    }

    float4 xv0 = __ldg((const float4*)(xF + (size_t)n * C) + 2 * ql);
    float4 xv1 = __ldg((const float4*)(xF + (size_t)n * C) + 2 * ql + 1);
    float4 o0, o1;
    o0.x = xv0.x / (1.f + __expf(-a0.x));
    o0.y = xv0.y / (1.f + __expf(-a0.y));
    o0.z = xv0.z / (1.f + __expf(-a0.z));
    o0.w = xv0.w / (1.f + __expf(-a0.w));
    o1.x = xv1.x / (1.f + __expf(-a1.x));
    o1.y = xv1.y / (1.f + __expf(-a1.y));
    o1.z = xv1.z / (1.f + __expf(-a1.z));
    o1.w = xv1.w / (1.f + __expf(-a1.w));
    ((float4*)(g_outse + (size_t)n * C))[2 * ql]     = o0;
    ((float4*)(g_outse + (size_t)n * C))[2 * ql + 1] = o1;

    // ---- rowsum/rowmax over the quarter ----
    float s  = (o0.x + o0.y + o0.z + o0.w) + (o1.x + o1.y + o1.z + o1.w);
    float mm = fmaxf(fmaxf(fmaxf(o0.x, o0.y), fmaxf(o0.z, o0.w)),
                     fmaxf(fmaxf(o1.x, o1.y), fmaxf(o1.z, o1.w)));
    #pragma unroll
    for (int off = 4; off >= 1; off >>= 1) {
        s  += __shfl_xor_sync(FULL, s, off);
        mm  = fmaxf(mm, __shfl_xor_sync(FULL, mm, off));
    }
    if (ql == 0)
        *(float2*)(g_rowstat + 2 * (size_t)n) = make_float2(s, mm);
}

// ---------------------------------------------------------------------------
// Kernel 2: z = (mean, max) pooled over neighbors, via per-point rowstats.
// ---------------------------------------------------------------------------
__global__ __launch_bounds__(256) void k2_z(const int* __restrict__ idx, int N)
{
    int n = blockIdx.x * blockDim.x + threadIdx.x;
    if (n >= N) return;
    const int4* ib = (const int4*)(idx + (size_t)n * KNN);
    int4 q0 = __ldg(ib + 0), q1 = __ldg(ib + 1),
         q2 = __ldg(ib + 2), q3 = __ldg(ib + 3);
    const int nb[KNN] = { q0.x, q0.y, q0.z, q0.w,  q1.x, q1.y, q1.z, q1.w,
                          q2.x, q2.y, q2.z, q2.w,  q3.x, q3.y, q3.z, q3.w };
    float s = 0.f, mx = -INFINITY;
    #pragma unroll
    for (int k = 0; k < KNN; k++) {
        float2 rs = __ldg((const float2*)(g_rowstat + 2 * (size_t)nb[k]));
        s += rs.x;
        mx = fmaxf(mx, rs.y);
    }
    *(float2*)(g_z + 2 * (size_t)n) = make_float2(s * (1.f / (KNN * C)), mx);
}

// ---------------------------------------------------------------------------
// Kernel 3a: sparse conv gate. TWO threads per point (14+13 taps each),
//            shfl-combined. Doubles grid -> fixes grid-limited occupancy.
// ---------------------------------------------------------------------------
__global__ __launch_bounds__(256) void k3a_gate(
    const float* __restrict__ conv_w,   // (27, 2)
    const int*   __restrict__ conv_idx, // (N, 27)
    int N)
{
    int t = blockIdx.x * blockDim.x + threadIdx.x;
    int n = t >> 1;
    int h = t & 1;
    if (n >= N) return;
    const int* cb = conv_idx + (size_t)n * 27;
    float f = 0.f;
    const int k0 = h ? 14 : 0;
    const int k1 = h ? 27 : 14;
    for (int k = k0; k < k1; k++) {
        int m = __ldg(cb + k);
        if (m >= 0) {
            float2 zz = __ldg((const float2*)g_z + m);
            float2 cw = __ldg((const float2*)conv_w + k);
            f += zz.x * cw.x + zz.y * cw.y;
        }
    }
    f += __shfl_xor_sync(FULL, f, 1);
    if (h == 0)
        g_gate[n] = 1.f / (1.f + __expf(-f));
}

// ---------------------------------------------------------------------------
// Kernel 3b: streaming multiply out = outse * gate (2 float4 per thread).
// ---------------------------------------------------------------------------
__global__ __launch_bounds__(256) void k3b_mul(float* __restrict__ out, int N)
{
    int t = blockIdx.x * blockDim.x + threadIdx.x;
    if (t >= N * 8) return;
    int n   = t >> 3;
    int seg = t & 7;
    float g = __ldg(g_gate + n);
    const float4* src = (const float4*)(g_outse + (size_t)n * C) + 2 * seg;
    float4 a = src[0], b = src[1];
    float4* dst = (float4*)(out + (size_t)n * C) + 2 * seg;
    dst[0] = make_float4(a.x * g, a.y * g, a.z * g, a.w * g);
    dst[1] = make_float4(b.x * g, b.y * g, b.z * g, b.w * g);
}

// ---------------------------------------------------------------------------
// Launch
// ---------------------------------------------------------------------------
extern "C" void kernel_launch(void* const* d_in, const int* in_sizes, int n_in,
                              void* d_out, int out_size)
{
    const float* xF  = (const float*)d_in[0];
    const float* W1  = (const float*)d_in[1];
    const float* b1  = (const float*)d_in[2];
    const float* W2  = (const float*)d_in[3];
    const float* b2  = (const float*)d_in[4];
    const float* cw  = (const float*)d_in[5];
    const int*   idx = (const int*)d_in[6];
    const int*   cid = (const int*)d_in[7];
    float*       out = (float*)d_out;

    const int N = in_sizes[0] / C;                 // 100000
    const int nquads    = (N + 3) / 4;             // 4 points per warp
    const int qw_blocks = (nquads + 7) / 8;        // 8 warps per block

    k0_prep<<<qw_blocks, 256>>>(xF, W1, N);
    k1_gate<<<qw_blocks, 256>>>(xF, W1, b1, W2, b2, idx, N);
    k2_z    <<<(N + 255) / 256, 256>>>(idx, N);
    k3a_gate<<<(2 * N + 255) / 256, 256>>>(cw, cid, N);
    k3b_mul <<<(N * 8 + 255) / 256, 256>>>(out, N);
}

// round 7
// speedup vs baseline: 1.2421x; 1.2421x over previous
#include <cuda_runtime.h>
#include <cuda_fp16.h>
#include <math.h>

#define NMAX 100000
#define C    64
#define HID  16
#define KNN  16
#define FULL 0xFFFFFFFFu

// Scratch (device globals)
__device__ float g_outse[(size_t)NMAX * C];
__device__ float g_rowstat[(size_t)NMAX * 2];
__device__ float g_z[(size_t)NMAX * 2];
__device__ __align__(16) __half2 g_xh2[(size_t)NMAX * C / 2]; // fp16 mirror of x_F

// ---------------------------------------------------------------------------
// Kernel 0: fp16 mirror of x_F (row = 128B = one cache line).
// ---------------------------------------------------------------------------
__global__ __launch_bounds__(256) void k0_tohalf(const float* __restrict__ xF, int n8)
{
    int i = blockIdx.x * blockDim.x + threadIdx.x;
    if (i >= n8) return;
    const float4* src = (const float4*)xF;
    float4 a = __ldg(src + 2 * i);
    float4 b = __ldg(src + 2 * i + 1);
    __half2 h0 = __floats2half2_rn(a.x, a.y);
    __half2 h1 = __floats2half2_rn(a.z, a.w);
    __half2 h2 = __floats2half2_rn(b.x, b.y);
    __half2 h3 = __floats2half2_rn(b.z, b.w);
    ((uint4*)g_xh2)[i] = make_uint4(*(unsigned*)&h0, *(unsigned*)&h1,
                                    *(unsigned*)&h2, *(unsigned*)&h3);
}

// ---------------------------------------------------------------------------
// Kernel 1: channel attention, QUARTER-WARP per point (4 points/warp).
//   q = lane>>3, ql = lane&7, lane owns channels 8ql..8ql+7.
//   Gather: 1 LDG.128 per k (fp16 row = 1 line). Max pooled with HMAX2
//   (exact), mean accumulated fp32. Layer-1 mean/max share weight loads;
//   one interleaved 32-value butterfly.
// ---------------------------------------------------------------------------
__global__ __launch_bounds__(256) void k1_gate(
    const float* __restrict__ xF,
    const float* __restrict__ W1,   // (C, HID)
    const float* __restrict__ b1,   // (HID,)
    const float* __restrict__ W2,   // (HID, C)
    const float* __restrict__ b2,   // (C,)
    const int*   __restrict__ idx,  // (N, KNN)
    int N)
{
    __shared__ float4 sW1a[HID * 8], sW1b[HID * 8];
    __shared__ float4 sW2a[HID * 8], sW2b[HID * 8];

    const int tid = threadIdx.x;
    for (int i = tid; i < HID * 8; i += blockDim.x) {
        int j = i >> 3, h = i & 7;
        sW1a[i] = make_float4(W1[(8*h+0)*HID + j], W1[(8*h+1)*HID + j],
                              W1[(8*h+2)*HID + j], W1[(8*h+3)*HID + j]);
        sW1b[i] = make_float4(W1[(8*h+4)*HID + j], W1[(8*h+5)*HID + j],
                              W1[(8*h+6)*HID + j], W1[(8*h+7)*HID + j]);
        sW2a[i] = __ldg((const float4*)W2 + j * 16 + 2 * h);
        sW2b[i] = __ldg((const float4*)W2 + j * 16 + 2 * h + 1);
    }
    __syncthreads();

    const int lane  = tid & 31;
    const int q     = lane >> 3;
    const int ql    = lane & 7;
    const int qbase = lane & 24;
    const int warp  = blockIdx.x * (blockDim.x >> 5) + (tid >> 5);
    if (4 * warp >= N) return;
    int n = 4 * warp + q;
    if (n >= N) n = N - 1;

    const float2 b1v = __ldg((const float2*)b1 + ql);
    const float4 b2a = __ldg((const float4*)b2 + 2 * ql);
    const float4 b2b = __ldg((const float4*)b2 + 2 * ql + 1);

    // ---- neighbor indices ----
    const int4* ib = (const int4*)(idx + (size_t)n * KNN);
    int4 i0 = __ldg(ib + 0), i1 = __ldg(ib + 1),
         i2 = __ldg(ib + 2), i3 = __ldg(ib + 3);
    const int nb[KNN] = { i0.x, i0.y, i0.z, i0.w,  i1.x, i1.y, i1.z, i1.w,
                          i2.x, i2.y, i2.z, i2.w,  i3.x, i3.y, i3.z, i3.w };

    // ---- gather + pool: HMAX2 max (exact), fp32 mean ----
    const __half NEGINF = __ushort_as_half((unsigned short)0xFC00);
    __half2 mh0 = __half2half2(NEGINF), mh1 = __half2half2(NEGINF);
    __half2 mh2 = __half2half2(NEGINF), mh3 = __half2half2(NEGINF);
    float m[8] = {0.f, 0.f, 0.f, 0.f, 0.f, 0.f, 0.f, 0.f};
    #pragma unroll
    for (int k = 0; k < KNN; k++) {
        uint4 raw = __ldg((const uint4*)(g_xh2 + (size_t)nb[k] * (C/2)) + ql);
        mh0 = __hmax2(mh0, *(__half2*)&raw.x);
        mh1 = __hmax2(mh1, *(__half2*)&raw.y);
        mh2 = __hmax2(mh2, *(__half2*)&raw.z);
        mh3 = __hmax2(mh3, *(__half2*)&raw.w);
        float2 f0 = __half22float2(*(__half2*)&raw.x);
        float2 f1 = __half22float2(*(__half2*)&raw.y);
        float2 f2 = __half22float2(*(__half2*)&raw.z);
        float2 f3 = __half22float2(*(__half2*)&raw.w);
        m[0] += f0.x; m[1] += f0.y; m[2] += f1.x; m[3] += f1.y;
        m[4] += f2.x; m[5] += f2.y; m[6] += f3.x; m[7] += f3.y;
    }
    const float inv = 1.f / KNN;
    #pragma unroll
    for (int i = 0; i < 8; i++) m[i] *= inv;

    float fx[8];
    { float2 c0 = __half22float2(mh0), c1 = __half22float2(mh1),
             c2 = __half22float2(mh2), c3 = __half22float2(mh3);
      fx[0]=c0.x; fx[1]=c0.y; fx[2]=c1.x; fx[3]=c1.y;
      fx[4]=c2.x; fx[5]=c2.y; fx[6]=c3.x; fx[7]=c3.y; }

    // ---- layer-1, mean/max fused (shared weight loads):
    //      p[2j] = mean-path unit j, p[2j+1] = max-path unit j ----
    float p[32];
    #pragma unroll
    for (int j = 0; j < HID; j++) {
        float4 wa = sW1a[j * 8 + ql], wb = sW1b[j * 8 + ql];
        p[2*j]   = m[0]*wa.x + m[1]*wa.y + m[2]*wa.z + m[3]*wa.w
                 + m[4]*wb.x + m[5]*wb.y + m[6]*wb.z + m[7]*wb.w;
        p[2*j+1] = fx[0]*wa.x + fx[1]*wa.y + fx[2]*wa.z + fx[3]*wa.w
                 + fx[4]*wb.x + fx[5]*wb.y + fx[6]*wb.z + fx[7]*wb.w;
    }

    // ---- 8-lane vector-halving butterfly over 32 values (28 shfls).
    //      Final: lane ql holds p[0..3] = elements 4ql..4ql+3, i.e.
    //      mean(2ql), max(2ql), mean(2ql+1), max(2ql+1). ----
    #pragma unroll
    for (int step = 0; step < 3; step++) {
        const int  off = 4 >> step;    // 4,2,1 (within quarter)
        const int  nv  = 16 >> step;   // 16,8,4
        const bool up  = (ql & off) != 0;
        #pragma unroll
        for (int i = 0; i < nv; i++) {
            float send = up ? p[i] : p[i + nv];
            float recv = __shfl_xor_sync(FULL, send, off);
            float keep = up ? p[i + nv] : p[i];
            p[i] = keep + recv;
        }
    }

    float hs0 = fmaxf(p[0] + b1v.x, 0.f) + fmaxf(p[1] + b1v.x, 0.f);
    float hs1 = fmaxf(p[2] + b1v.y, 0.f) + fmaxf(p[3] + b1v.y, 0.f);

    // ---- layer 2 ----
    float4 a0 = make_float4(2.f*b2a.x, 2.f*b2a.y, 2.f*b2a.z, 2.f*b2a.w);
    float4 a1 = make_float4(2.f*b2b.x, 2.f*b2b.y, 2.f*b2b.z, 2.f*b2b.w);
    #pragma unroll
    for (int jj = 0; jj < 8; jj++) {
        float h0 = __shfl_sync(FULL, hs0, qbase | jj);   // hidden 2jj
        float h1 = __shfl_sync(FULL, hs1, qbase | jj);   // hidden 2jj+1
        float4 wa = sW2a[(2*jj) * 8 + ql],   wb = sW2b[(2*jj) * 8 + ql];
        a0.x += h0*wa.x; a0.y += h0*wa.y; a0.z += h0*wa.z; a0.w += h0*wa.w;
        a1.x += h0*wb.x; a1.y += h0*wb.y; a1.z += h0*wb.z; a1.w += h0*wb.w;
        float4 wc = sW2a[(2*jj+1) * 8 + ql], wd = sW2b[(2*jj+1) * 8 + ql];
        a0.x += h1*wc.x; a0.y += h1*wc.y; a0.z += h1*wc.z; a0.w += h1*wc.w;
        a1.x += h1*wd.x; a1.y += h1*wd.y; a1.z += h1*wd.z; a1.w += h1*wd.w;
    }

    float4 xv0 = __ldg((const float4*)(xF + (size_t)n * C) + 2 * ql);
    float4 xv1 = __ldg((const float4*)(xF + (size_t)n * C) + 2 * ql + 1);
    float4 o0, o1;
    o0.x = xv0.x / (1.f + __expf(-a0.x));
    o0.y = xv0.y / (1.f + __expf(-a0.y));
    o0.z = xv0.z / (1.f + __expf(-a0.z));
    o0.w = xv0.w / (1.f + __expf(-a0.w));
    o1.x = xv1.x / (1.f + __expf(-a1.x));
    o1.y = xv1.y / (1.f + __expf(-a1.y));
    o1.z = xv1.z / (1.f + __expf(-a1.z));
    o1.w = xv1.w / (1.f + __expf(-a1.w));
    ((float4*)(g_outse + (size_t)n * C))[2 * ql]     = o0;
    ((float4*)(g_outse + (size_t)n * C))[2 * ql + 1] = o1;

    // ---- rowsum/rowmax over the quarter ----
    float s  = (o0.x + o0.y + o0.z + o0.w) + (o1.x + o1.y + o1.z + o1.w);
    float mm = fmaxf(fmaxf(fmaxf(o0.x, o0.y), fmaxf(o0.z, o0.w)),
                     fmaxf(fmaxf(o1.x, o1.y), fmaxf(o1.z, o1.w)));
    #pragma unroll
    for (int off = 4; off >= 1; off >>= 1) {
        s  += __shfl_xor_sync(FULL, s, off);
        mm  = fmaxf(mm, __shfl_xor_sync(FULL, mm, off));
    }
    if (ql == 0)
        *(float2*)(g_rowstat + 2 * (size_t)n) = make_float2(s, mm);
}

// ---------------------------------------------------------------------------
// Kernel 2: z = (mean, max) pooled over neighbors, via per-point rowstats.
// ---------------------------------------------------------------------------
__global__ __launch_bounds__(256) void k2_z(const int* __restrict__ idx, int N)
{
    int n = blockIdx.x * blockDim.x + threadIdx.x;
    if (n >= N) return;
    const int4* ib = (const int4*)(idx + (size_t)n * KNN);
    int4 q0 = __ldg(ib + 0), q1 = __ldg(ib + 1),
         q2 = __ldg(ib + 2), q3 = __ldg(ib + 3);
    const int nb[KNN] = { q0.x, q0.y, q0.z, q0.w,  q1.x, q1.y, q1.z, q1.w,
                          q2.x, q2.y, q2.z, q2.w,  q3.x, q3.y, q3.z, q3.w };
    float s = 0.f, mx = -INFINITY;
    #pragma unroll
    for (int k = 0; k < KNN; k++) {
        float2 rs = __ldg((const float2*)(g_rowstat + 2 * (size_t)nb[k]));
        s += rs.x;
        mx = fmaxf(mx, rs.y);
    }
    *(float2*)(g_z + 2 * (size_t)n) = make_float2(s * (1.f / (KNN * C)), mx);
}

// ---------------------------------------------------------------------------
// Kernel 3 (fused gate + multiply): QUARTER-WARP per point.
//   Lane ql handles conv taps 4ql..4ql+3 (<=4-deep chains), 3-shfl reduce,
//   then each lane applies the gate to its 8 channels.
// ---------------------------------------------------------------------------
__global__ __launch_bounds__(256) void k3_fused(
    const float* __restrict__ conv_w,   // (27, 2)
    const int*   __restrict__ conv_idx, // (N, 27)
    float*       __restrict__ out,
    int N)
{
    __shared__ float2 scw[27];
    if (threadIdx.x < 27)
        scw[threadIdx.x] = __ldg((const float2*)conv_w + threadIdx.x);
    __syncthreads();

    const int lane = threadIdx.x & 31;
    const int q    = lane >> 3;
    const int ql   = lane & 7;
    const int warp = blockIdx.x * (blockDim.x >> 5) + (threadIdx.x >> 5);
    if (4 * warp >= N) return;
    int n = 4 * warp + q;
    if (n >= N) n = N - 1;

    const int* cb = conv_idx + (size_t)n * 27;
    float f = 0.f;
    #pragma unroll
    for (int i = 0; i < 4; i++) {
        int k = 4 * ql + i;
        if (k < 27) {
            int m = __ldg(cb + k);
            if (m >= 0) {
                float2 zz = __ldg((const float2*)g_z + m);
                float2 cw = scw[k];
                f += zz.x * cw.x + zz.y * cw.y;
            }
        }
    }
    #pragma unroll
    for (int off = 4; off >= 1; off >>= 1)
        f += __shfl_xor_sync(FULL, f, off);

    float sg = 1.f / (1.f + __expf(-f));
    float4 a = ((const float4*)(g_outse + (size_t)n * C))[2 * ql];
    float4 b = ((const float4*)(g_outse + (size_t)n * C))[2 * ql + 1];
    ((float4*)(out + (size_t)n * C))[2 * ql] =
        make_float4(a.x * sg, a.y * sg, a.z * sg, a.w * sg);
    ((float4*)(out + (size_t)n * C))[2 * ql + 1] =
        make_float4(b.x * sg, b.y * sg, b.z * sg, b.w * sg);
}

// ---------------------------------------------------------------------------
// Launch
// ---------------------------------------------------------------------------
extern "C" void kernel_launch(void* const* d_in, const int* in_sizes, int n_in,
                              void* d_out, int out_size)
{
    const float* xF  = (const float*)d_in[0];
    const float* W1  = (const float*)d_in[1];
    const float* b1  = (const float*)d_in[2];
    const float* W2  = (const float*)d_in[3];
    const float* b2  = (const float*)d_in[4];
    const float* cw  = (const float*)d_in[5];
    const int*   idx = (const int*)d_in[6];
    const int*   cid = (const int*)d_in[7];
    float*       out = (float*)d_out;

    const int N  = in_sizes[0] / C;                // 100000
    const int n8 = (N * C) / 8;
    const int nquads    = (N + 3) / 4;             // 4 points per warp
    const int qw_blocks = (nquads + 7) / 8;        // 8 warps per block

    k0_tohalf<<<(n8 + 255) / 256, 256>>>(xF, n8);
    k1_gate  <<<qw_blocks, 256>>>(xF, W1, b1, W2, b2, idx, N);
    k2_z     <<<(N + 255) / 256, 256>>>(idx, N);
    k3_fused <<<qw_blocks, 256>>>(cw, cid, out, N);
}

// round 8
// speedup vs baseline: 1.2484x; 1.0051x over previous
#include <cuda_runtime.h>
#include <cuda_fp16.h>
#include <math.h>

#define NMAX 100000
#define C    64
#define HID  16
#define KNN  16
#define FULL 0xFFFFFFFFu

// Scratch (device globals)
__device__ float g_outse[(size_t)NMAX * C];
__device__ float g_rowstat[(size_t)NMAX * 2];
__device__ float g_z[(size_t)NMAX * 2];
__device__ __align__(16) __half2 g_xh2[(size_t)NMAX * C / 2]; // fp16 mirror of x_F

// ---------------------------------------------------------------------------
// Kernel 0: fp16 mirror of x_F (row = 128B = one cache line).
// ---------------------------------------------------------------------------
__global__ __launch_bounds__(256) void k0_tohalf(const float* __restrict__ xF, int n8)
{
    int i = blockIdx.x * blockDim.x + threadIdx.x;
    if (i >= n8) return;
    const float4* src = (const float4*)xF;
    float4 a = __ldg(src + 2 * i);
    float4 b = __ldg(src + 2 * i + 1);
    __half2 h0 = __floats2half2_rn(a.x, a.y);
    __half2 h1 = __floats2half2_rn(a.z, a.w);
    __half2 h2 = __floats2half2_rn(b.x, b.y);
    __half2 h3 = __floats2half2_rn(b.z, b.w);
    ((uint4*)g_xh2)[i] = make_uint4(*(unsigned*)&h0, *(unsigned*)&h1,
                                    *(unsigned*)&h2, *(unsigned*)&h3);
}

// ---------------------------------------------------------------------------
// Kernel 1: channel attention, QUARTER-WARP per point (4 points/warp).
//   q = lane>>3, ql = lane&7, lane owns channels 8ql..8ql+7.
//   Gather loop per k: 1 LDG.128 + 4 HMAX2 (exact max) + 4 HADD2 (fp16 mean
//   sum; one conversion after the loop). No other per-k arithmetic.
// ---------------------------------------------------------------------------
__global__ __launch_bounds__(256) void k1_gate(
    const float* __restrict__ xF,
    const float* __restrict__ W1,   // (C, HID)
    const float* __restrict__ b1,   // (HID,)
    const float* __restrict__ W2,   // (HID, C)
    const float* __restrict__ b2,   // (C,)
    const int*   __restrict__ idx,  // (N, KNN)
    int N)
{
    __shared__ float4 sW1a[HID * 8], sW1b[HID * 8];
    __shared__ float4 sW2a[HID * 8], sW2b[HID * 8];

    const int tid = threadIdx.x;
    for (int i = tid; i < HID * 8; i += blockDim.x) {
        int j = i >> 3, h = i & 7;
        sW1a[i] = make_float4(W1[(8*h+0)*HID + j], W1[(8*h+1)*HID + j],
                              W1[(8*h+2)*HID + j], W1[(8*h+3)*HID + j]);
        sW1b[i] = make_float4(W1[(8*h+4)*HID + j], W1[(8*h+5)*HID + j],
                              W1[(8*h+6)*HID + j], W1[(8*h+7)*HID + j]);
        sW2a[i] = __ldg((const float4*)W2 + j * 16 + 2 * h);
        sW2b[i] = __ldg((const float4*)W2 + j * 16 + 2 * h + 1);
    }
    __syncthreads();

    const int lane  = tid & 31;
    const int q     = lane >> 3;
    const int ql    = lane & 7;
    const int qbase = lane & 24;
    const int warp  = blockIdx.x * (blockDim.x >> 5) + (tid >> 5);
    if (4 * warp >= N) return;
    int n = 4 * warp + q;
    if (n >= N) n = N - 1;

    const float2 b1v = __ldg((const float2*)b1 + ql);
    const float4 b2a = __ldg((const float4*)b2 + 2 * ql);
    const float4 b2b = __ldg((const float4*)b2 + 2 * ql + 1);

    // independent of the gather: issue early to overlap
    float4 xv0 = __ldg((const float4*)(xF + (size_t)n * C) + 2 * ql);
    float4 xv1 = __ldg((const float4*)(xF + (size_t)n * C) + 2 * ql + 1);

    // ---- neighbor indices ----
    const int4* ib = (const int4*)(idx + (size_t)n * KNN);
    int4 i0 = __ldg(ib + 0), i1 = __ldg(ib + 1),
         i2 = __ldg(ib + 2), i3 = __ldg(ib + 3);
    const int nb[KNN] = { i0.x, i0.y, i0.z, i0.w,  i1.x, i1.y, i1.z, i1.w,
                          i2.x, i2.y, i2.z, i2.w,  i3.x, i3.y, i3.z, i3.w };

    // ---- gather + pool: all pooling in native half2 ----
    const __half NEGINF = __ushort_as_half((unsigned short)0xFC00);
    __half2 mh0 = __half2half2(NEGINF), mh1 = __half2half2(NEGINF);
    __half2 mh2 = __half2half2(NEGINF), mh3 = __half2half2(NEGINF);
    __half2 sh0 = __float2half2_rn(0.f), sh1 = __float2half2_rn(0.f);
    __half2 sh2 = __float2half2_rn(0.f), sh3 = __float2half2_rn(0.f);
    #pragma unroll
    for (int k = 0; k < KNN; k++) {
        uint4 raw = __ldg((const uint4*)(g_xh2 + (size_t)nb[k] * (C/2)) + ql);
        __half2 r0 = *(__half2*)&raw.x, r1 = *(__half2*)&raw.y;
        __half2 r2 = *(__half2*)&raw.z, r3 = *(__half2*)&raw.w;
        mh0 = __hmax2(mh0, r0); mh1 = __hmax2(mh1, r1);
        mh2 = __hmax2(mh2, r2); mh3 = __hmax2(mh3, r3);
        sh0 = __hadd2(sh0, r0); sh1 = __hadd2(sh1, r1);
        sh2 = __hadd2(sh2, r2); sh3 = __hadd2(sh3, r3);
    }

    // one conversion block after the loop
    float m[8], fx[8];
    { const float inv = 1.f / KNN;
      float2 s0 = __half22float2(sh0), s1 = __half22float2(sh1),
             s2 = __half22float2(sh2), s3 = __half22float2(sh3);
      m[0]=s0.x*inv; m[1]=s0.y*inv; m[2]=s1.x*inv; m[3]=s1.y*inv;
      m[4]=s2.x*inv; m[5]=s2.y*inv; m[6]=s3.x*inv; m[7]=s3.y*inv;
      float2 c0 = __half22float2(mh0), c1 = __half22float2(mh1),
             c2 = __half22float2(mh2), c3 = __half22float2(mh3);
      fx[0]=c0.x; fx[1]=c0.y; fx[2]=c1.x; fx[3]=c1.y;
      fx[4]=c2.x; fx[5]=c2.y; fx[6]=c3.x; fx[7]=c3.y; }

    // ---- layer-1, mean/max fused (shared weight loads):
    //      p[2j] = mean-path unit j, p[2j+1] = max-path unit j ----
    float p[32];
    #pragma unroll
    for (int j = 0; j < HID; j++) {
        float4 wa = sW1a[j * 8 + ql], wb = sW1b[j * 8 + ql];
        p[2*j]   = m[0]*wa.x + m[1]*wa.y + m[2]*wa.z + m[3]*wa.w
                 + m[4]*wb.x + m[5]*wb.y + m[6]*wb.z + m[7]*wb.w;
        p[2*j+1] = fx[0]*wa.x + fx[1]*wa.y + fx[2]*wa.z + fx[3]*wa.w
                 + fx[4]*wb.x + fx[5]*wb.y + fx[6]*wb.z + fx[7]*wb.w;
    }

    // ---- 8-lane vector-halving butterfly over 32 values (28 shfls).
    //      Final: lane ql holds p[0..3] = elements 4ql..4ql+3, i.e.
    //      mean(2ql), max(2ql), mean(2ql+1), max(2ql+1). ----
    #pragma unroll
    for (int step = 0; step < 3; step++) {
        const int  off = 4 >> step;    // 4,2,1 (within quarter)
        const int  nv  = 16 >> step;   // 16,8,4
        const bool up  = (ql & off) != 0;
        #pragma unroll
        for (int i = 0; i < nv; i++) {
            float send = up ? p[i] : p[i + nv];
            float recv = __shfl_xor_sync(FULL, send, off);
            float keep = up ? p[i + nv] : p[i];
            p[i] = keep + recv;
        }
    }

    float hs0 = fmaxf(p[0] + b1v.x, 0.f) + fmaxf(p[1] + b1v.x, 0.f);
    float hs1 = fmaxf(p[2] + b1v.y, 0.f) + fmaxf(p[3] + b1v.y, 0.f);

    // ---- layer 2 ----
    float4 a0 = make_float4(2.f*b2a.x, 2.f*b2a.y, 2.f*b2a.z, 2.f*b2a.w);
    float4 a1 = make_float4(2.f*b2b.x, 2.f*b2b.y, 2.f*b2b.z, 2.f*b2b.w);
    #pragma unroll
    for (int jj = 0; jj < 8; jj++) {
        float h0 = __shfl_sync(FULL, hs0, qbase | jj);   // hidden 2jj
        float h1 = __shfl_sync(FULL, hs1, qbase | jj);   // hidden 2jj+1
        float4 wa = sW2a[(2*jj) * 8 + ql],   wb = sW2b[(2*jj) * 8 + ql];
        a0.x += h0*wa.x; a0.y += h0*wa.y; a0.z += h0*wa.z; a0.w += h0*wa.w;
        a1.x += h0*wb.x; a1.y += h0*wb.y; a1.z += h0*wb.z; a1.w += h0*wb.w;
        float4 wc = sW2a[(2*jj+1) * 8 + ql], wd = sW2b[(2*jj+1) * 8 + ql];
        a0.x += h1*wc.x; a0.y += h1*wc.y; a0.z += h1*wc.z; a0.w += h1*wc.w;
        a1.x += h1*wd.x; a1.y += h1*wd.y; a1.z += h1*wd.z; a1.w += h1*wd.w;
    }

    float4 o0, o1;
    o0.x = xv0.x / (1.f + __expf(-a0.x));
    o0.y = xv0.y / (1.f + __expf(-a0.y));
    o0.z = xv0.z / (1.f + __expf(-a0.z));
    o0.w = xv0.w / (1.f + __expf(-a0.w));
    o1.x = xv1.x / (1.f + __expf(-a1.x));
    o1.y = xv1.y / (1.f + __expf(-a1.y));
    o1.z = xv1.z / (1.f + __expf(-a1.z));
    o1.w = xv1.w / (1.f + __expf(-a1.w));
    ((float4*)(g_outse + (size_t)n * C))[2 * ql]     = o0;
    ((float4*)(g_outse + (size_t)n * C))[2 * ql + 1] = o1;

    // ---- rowsum/rowmax over the quarter ----
    float s  = (o0.x + o0.y + o0.z + o0.w) + (o1.x + o1.y + o1.z + o1.w);
    float mm = fmaxf(fmaxf(fmaxf(o0.x, o0.y), fmaxf(o0.z, o0.w)),
                     fmaxf(fmaxf(o1.x, o1.y), fmaxf(o1.z, o1.w)));
    #pragma unroll
    for (int off = 4; off >= 1; off >>= 1) {
        s  += __shfl_xor_sync(FULL, s, off);
        mm  = fmaxf(mm, __shfl_xor_sync(FULL, mm, off));
    }
    if (ql == 0)
        *(float2*)(g_rowstat + 2 * (size_t)n) = make_float2(s, mm);
}

// ---------------------------------------------------------------------------
// Kernel 2: z = (mean, max) pooled over neighbors, via per-point rowstats.
// ---------------------------------------------------------------------------
__global__ __launch_bounds__(256) void k2_z(const int* __restrict__ idx, int N)
{
    int n = blockIdx.x * blockDim.x + threadIdx.x;
    if (n >= N) return;
    const int4* ib = (const int4*)(idx + (size_t)n * KNN);
    int4 q0 = __ldg(ib + 0), q1 = __ldg(ib + 1),
         q2 = __ldg(ib + 2), q3 = __ldg(ib + 3);
    const int nb[KNN] = { q0.x, q0.y, q0.z, q0.w,  q1.x, q1.y, q1.z, q1.w,
                          q2.x, q2.y, q2.z, q2.w,  q3.x, q3.y, q3.z, q3.w };
    float s = 0.f, mx = -INFINITY;
    #pragma unroll
    for (int k = 0; k < KNN; k++) {
        float2 rs = __ldg((const float2*)(g_rowstat + 2 * (size_t)nb[k]));
        s += rs.x;
        mx = fmaxf(mx, rs.y);
    }
    *(float2*)(g_z + 2 * (size_t)n) = make_float2(s * (1.f / (KNN * C)), mx);
}

// ---------------------------------------------------------------------------
// Kernel 3 (fused gate + multiply): QUARTER-WARP per point.
//   outse streaming loads issued BEFORE the serial conv-tap chain.
// ---------------------------------------------------------------------------
__global__ __launch_bounds__(256) void k3_fused(
    const float* __restrict__ conv_w,   // (27, 2)
    const int*   __restrict__ conv_idx, // (N, 27)
    float*       __restrict__ out,
    int N)
{
    __shared__ float2 scw[27];
    if (threadIdx.x < 27)
        scw[threadIdx.x] = __ldg((const float2*)conv_w + threadIdx.x);
    __syncthreads();

    const int lane = threadIdx.x & 31;
    const int q    = lane >> 3;
    const int ql   = lane & 7;
    const int warp = blockIdx.x * (blockDim.x >> 5) + (threadIdx.x >> 5);
    if (4 * warp >= N) return;
    int n = 4 * warp + q;
    if (n >= N) n = N - 1;

    // independent streaming loads first (overlap with conv gather latency)
    float4 a = ((const float4*)(g_outse + (size_t)n * C))[2 * ql];
    float4 b = ((const float4*)(g_outse + (size_t)n * C))[2 * ql + 1];

    const int* cb = conv_idx + (size_t)n * 27;
    float f = 0.f;
    #pragma unroll
    for (int i = 0; i < 4; i++) {
        int k = 4 * ql + i;
        if (k < 27) {
            int m = __ldg(cb + k);
            if (m >= 0) {
                float2 zz = __ldg((const float2*)g_z + m);
                float2 cw = scw[k];
                f += zz.x * cw.x + zz.y * cw.y;
            }
        }
    }
    #pragma unroll
    for (int off = 4; off >= 1; off >>= 1)
        f += __shfl_xor_sync(FULL, f, off);

    float sg = 1.f / (1.f + __expf(-f));
    ((float4*)(out + (size_t)n * C))[2 * ql] =
        make_float4(a.x * sg, a.y * sg, a.z * sg, a.w * sg);
    ((float4*)(out + (size_t)n * C))[2 * ql + 1] =
        make_float4(b.x * sg, b.y * sg, b.z * sg, b.w * sg);
}

// ---------------------------------------------------------------------------
// Launch
// ---------------------------------------------------------------------------
extern "C" void kernel_launch(void* const* d_in, const int* in_sizes, int n_in,
                              void* d_out, int out_size)
{
    const float* xF  = (const float*)d_in[0];
    const float* W1  = (const float*)d_in[1];
    const float* b1  = (const float*)d_in[2];
    const float* W2  = (const float*)d_in[3];
    const float* b2  = (const float*)d_in[4];
    const float* cw  = (const float*)d_in[5];
    const int*   idx = (const int*)d_in[6];
    const int*   cid = (const int*)d_in[7];
    float*       out = (float*)d_out;

    const int N  = in_sizes[0] / C;                // 100000
    const int n8 = (N * C) / 8;
    const int nquads    = (N + 3) / 4;             // 4 points per warp
    const int qw_blocks = (nquads + 7) / 8;        // 8 warps per block

    k0_tohalf<<<(n8 + 255) / 256, 256>>>(xF, n8);
    k1_gate  <<<qw_blocks, 256>>>(xF, W1, b1, W2, b2, idx, N);
    k2_z     <<<(N + 255) / 256, 256>>>(idx, N);
    k3_fused <<<qw_blocks, 256>>>(cw, cid, out, N);
}